// round 8
// baseline (speedup 1.0000x reference)
#include <cuda_runtime.h>
#include <cstdint>

// ---------------------------------------------------------------------------
// STN: conv(3x3)+relu+pool x3 -> mean -> dense x3 -> theta -> bilinear sample
// ---------------------------------------------------------------------------

typedef unsigned long long ull;

__device__ float g_pool1[16 * 127 * 127 * 16];
__device__ float g_pool2[16 * 62 * 62 * 32];
__device__ float g_mean[16 * 32];
__device__ float g_theta[16 * 6];

__device__ __forceinline__ void fma2(ull& d, ull a, ull b) {
    asm("fma.rn.f32x2 %0, %1, %2, %0;" : "+l"(d) : "l"(a), "l"(b));
}
__device__ __forceinline__ float2 asF2(ull v) {
    float2 r;
    r.x = __uint_as_float((unsigned)(v & 0xffffffffULL));
    r.y = __uint_as_float((unsigned)(v >> 32));
    return r;
}

// ---------------------------------------------------------------------------
// Fused conv3x3(VALID)+bias+relu+maxpool2 (+optional mean accumulation)
// fp32x2 packed over input-channel pairs; horizontal add at the end.
// Each thread: 2x4 conv positions (= 1x2 pooled pixels) x 4 output channels.
// Block: 256 thr = 4 x-slots * TILE_PY y-slots * GROUPS channel groups.
// Pooled tile: 8 wide x TILE_PY tall. 2 blocks/SM (RF-limited), 16 warps/SM.
// ---------------------------------------------------------------------------
template<int CIN, int COUT, int GROUPS, int TILE_PY>
__global__ __launch_bounds__(256, 2)
void conv_pool_kernel(const float* __restrict__ in, int inDim,
                      const float* __restrict__ w, const float* __restrict__ bias,
                      float* __restrict__ out, int outDim, int tilesX,
                      float* __restrict__ meanAcc)
{
    constexpr int THREADS = 256;
    constexpr int NC   = COUT / GROUPS;     // = 4 channels per thread
    constexpr int ISTR = CIN + 2;           // even, ISTR/2 odd -> bank spread
    constexpr int WSTR = CIN + 2;
    constexpr int TW   = 18;                // input tile width (16 conv cols + 2)
    constexpr int TH   = 2 * TILE_PY + 2;   // input tile height
    extern __shared__ float smem[];
    float* sIn = smem;                      // TH*TW*ISTR
    float* sW  = smem + TH * TW * ISTR;     // 9*COUT*WSTR
    __shared__ float sMean[COUT];

    const int tid = threadIdx.x;
    const int b  = blockIdx.y;
    const int tX = blockIdx.x % tilesX;
    const int tY = blockIdx.x / tilesX;
    const int y0 = tY * TILE_PY * 2, x0 = tX * 16;

    // ---- weights: w[k][ci][co] -> sW[k][co][ci] ----
    constexpr int WTOT = 9 * CIN * COUT;
    for (int i = tid; i < WTOT; i += THREADS) {
        int co = i % COUT;
        int rest = i / COUT;
        int ci = rest % CIN;
        int k  = rest / CIN;
        sW[(k * COUT + co) * WSTR + ci] = w[i];
    }

    // ---- input window THxTWxCIN (channel-contiguous) ----
    constexpr int NCI4 = CIN / 4;
    for (int i = tid; i < TH * TW * NCI4; i += THREADS) {
        int ci4 = i % NCI4;
        int p   = i / NCI4;
        int ly = p / TW, lx = p - ly * TW;
        int gy = y0 + ly, gx = x0 + lx;
        float4 v = make_float4(0.f, 0.f, 0.f, 0.f);
        if (gy < inDim && gx < inDim)
            v = *(const float4*)(in + ((size_t)((b * inDim + gy) * inDim + gx)) * CIN + ci4 * 4);
        float* d = sIn + p * ISTR + ci4 * 4;        // 8B-aligned (ISTR even)
        *(ull*)(d)     = *(const ull*)&v.x;
        *(ull*)(d + 2) = *(const ull*)&v.z;
    }
    __syncthreads();

    const int g    = tid % GROUPS;
    const int slot = tid / GROUPS;
    const int sx   = slot % 4;              // covers conv cols 4sx..4sx+3
    const int py   = slot / 4;              // pooled row within tile

    ull acc[2][4][NC];
    #pragma unroll
    for (int i = 0; i < 2; i++)
        #pragma unroll
        for (int j = 0; j < 4; j++)
            #pragma unroll
            for (int k = 0; k < NC; k++) acc[i][j][k] = 0ULL;

    const float* ibase = sIn + ((2 * py) * TW + 4 * sx) * ISTR;
    const float* wbase = sW + g * WSTR;

    #pragma unroll 1
    for (int c2 = 0; c2 < CIN / 2; ++c2) {
        ull win[4][6];
        #pragma unroll
        for (int r = 0; r < 4; ++r)
            #pragma unroll
            for (int c = 0; c < 6; ++c)
                win[r][c] = *(const ull*)(ibase + (r * TW + c) * ISTR + 2 * c2);
        #pragma unroll
        for (int t = 0; t < 9; ++t) {
            const int ky = t / 3, kx = t % 3;
            #pragma unroll
            for (int cc = 0; cc < NC; ++cc) {
                ull w2 = *(const ull*)(wbase + (t * COUT + GROUPS * cc) * WSTR + 2 * c2);
                #pragma unroll
                for (int pr = 0; pr < 2; ++pr)
                    #pragma unroll
                    for (int pc = 0; pc < 4; ++pc)
                        fma2(acc[pr][pc][cc], win[pr + ky][pc + kx], w2);
            }
        }
    }

    // ---- horizontal add + relu(max2x2 + bias), two pooled pixels ----
    const int p = tY * TILE_PY + py;
    if (meanAcc) {
        if (tid < COUT) sMean[tid] = 0.f;
        __syncthreads();
    }
    #pragma unroll
    for (int j = 0; j < 2; ++j) {
        const int q = tX * 8 + 2 * sx + j;
        const bool valid = (p < outDim) && (q < outDim);
        float res[NC];
        #pragma unroll
        for (int cc = 0; cc < NC; ++cc) {
            float2 v00 = asF2(acc[0][2 * j][cc]);
            float2 v01 = asF2(acc[0][2 * j + 1][cc]);
            float2 v10 = asF2(acc[1][2 * j][cc]);
            float2 v11 = asF2(acc[1][2 * j + 1][cc]);
            float s0 = v00.x + v00.y, s1 = v01.x + v01.y;
            float s2 = v10.x + v10.y, s3 = v11.x + v11.y;
            res[cc] = fmaxf(fmaxf(fmaxf(s0, s1), fmaxf(s2, s3)) + bias[g + GROUPS * cc], 0.f);
        }
        if (out && valid) {
            float* o = out + ((size_t)((b * outDim + p) * outDim + q)) * COUT;
            #pragma unroll
            for (int cc = 0; cc < NC; ++cc) o[g + GROUPS * cc] = res[cc];
        }
        if (meanAcc && valid) {
            #pragma unroll
            for (int cc = 0; cc < NC; ++cc)
                atomicAdd(&sMean[g + GROUPS * cc], res[cc]);
        }
    }
    if (meanAcc) {
        __syncthreads();
        if (tid < COUT) atomicAdd(&meanAcc[b * COUT + tid], sMean[tid]);
    }
}

// ---------------------------------------------------------------------------
__global__ void zero_mean_kernel() { g_mean[threadIdx.x] = 0.f; }

__global__ void head_kernel(const float* __restrict__ D1, const float* __restrict__ db1,
                            const float* __restrict__ D2, const float* __restrict__ db2,
                            const float* __restrict__ D3, const float* __restrict__ db3)
{
    __shared__ float h0[16 * 32], h1[16 * 64], h2[16 * 32];
    int tid = threadIdx.x; // 256

    for (int i = tid; i < 512; i += 256) h0[i] = g_mean[i] * (1.0f / 900.0f);
    __syncthreads();

    for (int i = tid; i < 16 * 64; i += 256) {
        int bb = i >> 6, j = i & 63;
        float s = db1[j];
        #pragma unroll 8
        for (int c = 0; c < 32; c++) s += h0[bb * 32 + c] * D1[c * 64 + j];
        h1[i] = fmaxf(s, 0.f);
    }
    __syncthreads();

    for (int i = tid; i < 512; i += 256) {
        int bb = i >> 5, j = i & 31;
        float s = db2[j];
        #pragma unroll 8
        for (int c = 0; c < 64; c++) s += h1[bb * 64 + c] * D2[c * 32 + j];
        h2[i] = fmaxf(s, 0.f);
    }
    __syncthreads();

    if (tid < 96) {
        int bb = tid / 6, j = tid % 6;
        float s = db3[j];
        #pragma unroll 8
        for (int c = 0; c < 32; c++) s += h2[bb * 32 + c] * D3[c * 6 + j];
        g_theta[tid] = s;
    }
}

// ---------------------------------------------------------------------------
__global__ __launch_bounds__(256)
void sampler_kernel(const float* __restrict__ x, float* __restrict__ out)
{
    int t = blockIdx.x * 256 + threadIdx.x;
    int lane = t & 7;
    int pix  = t >> 3;
    int c = pix & 255;
    int r = (pix >> 8) & 255;
    int b = pix >> 16;

    const float* th = g_theta + b * 6;
    float xs = -1.f + (float)c * (2.f / 255.f);
    float ys = -1.f + (float)r * (2.f / 255.f);
    float xS = th[0] * xs + th[1] * ys + th[2];
    float yS = th[3] * xs + th[4] * ys + th[5];
    float xf = 0.5f * ((xS + 1.f) * 254.f);
    float yf = 0.5f * ((yS + 1.f) * 254.f);

    int ix0 = (int)floorf(xf), iy0 = (int)floorf(yf);
    int ix1 = ix0 + 1, iy1 = iy0 + 1;
    ix0 = min(max(ix0, 0), 255); ix1 = min(max(ix1, 0), 255);
    iy0 = min(max(iy0, 0), 255); iy1 = min(max(iy1, 0), 255);

    float X0 = (float)ix0, X1 = (float)ix1, Y0 = (float)iy0, Y1 = (float)iy1;
    float wa = (X1 - xf) * (Y1 - yf);
    float wb = (X1 - xf) * (yf - Y0);
    float wc = (xf - X0) * (Y1 - yf);
    float wd = (xf - X0) * (yf - Y0);

    const float4* pa = (const float4*)(x + ((size_t)((b * 256 + iy0) * 256 + ix0)) * 32) + lane;
    const float4* pb = (const float4*)(x + ((size_t)((b * 256 + iy1) * 256 + ix0)) * 32) + lane;
    const float4* pc = (const float4*)(x + ((size_t)((b * 256 + iy0) * 256 + ix1)) * 32) + lane;
    const float4* pd = (const float4*)(x + ((size_t)((b * 256 + iy1) * 256 + ix1)) * 32) + lane;
    float4 Ia = *pa, Ib = *pb, Ic = *pc, Id = *pd;

    float4 o;
    o.x = wa * Ia.x + wb * Ib.x + wc * Ic.x + wd * Id.x;
    o.y = wa * Ia.y + wb * Ib.y + wc * Ic.y + wd * Id.y;
    o.z = wa * Ia.z + wb * Ib.z + wc * Ic.z + wd * Id.z;
    o.w = wa * Ia.w + wb * Ib.w + wc * Ic.w + wd * Id.w;
    ((float4*)out)[t] = o;
}

// ---------------------------------------------------------------------------
extern "C" void kernel_launch(void* const* d_in, const int* in_sizes, int n_in,
                              void* d_out, int out_size)
{
    const float* x   = (const float*)d_in[0];
    const float* W1  = (const float*)d_in[1];
    const float* b1  = (const float*)d_in[2];
    const float* W2  = (const float*)d_in[3];
    const float* b2  = (const float*)d_in[4];
    const float* W3  = (const float*)d_in[5];
    const float* b3  = (const float*)d_in[6];
    const float* D1  = (const float*)d_in[7];
    const float* db1 = (const float*)d_in[8];
    const float* D2  = (const float*)d_in[9];
    const float* db2 = (const float*)d_in[10];
    const float* D3  = (const float*)d_in[11];
    const float* db3 = (const float*)d_in[12];
    float* out = (float*)d_out;

    float *p1, *p2, *mean_;
    cudaGetSymbolAddress((void**)&p1, g_pool1);
    cudaGetSymbolAddress((void**)&p2, g_pool2);
    cudaGetSymbolAddress((void**)&mean_, g_mean);

    // smem (floats): input TH*TW*(CIN+2) + weights 9*COUT*(CIN+2)
    const int SMEM1 = (34 * 18 * 34 + 9 * 16 * 34) * 4;   // 102816 -> 2 blocks/SM
    const int SMEM2 = (18 * 18 * 18 + 9 * 32 * 18) * 4;   //  44064 -> 2 blocks (RF)
    const int SMEM3 = (18 * 18 * 34 + 9 * 32 * 34) * 4;   //  83232 -> 2 blocks/SM
    cudaFuncSetAttribute((const void*)conv_pool_kernel<32, 16, 4, 16>,
                         cudaFuncAttributeMaxDynamicSharedMemorySize, SMEM1);
    cudaFuncSetAttribute((const void*)conv_pool_kernel<16, 32, 8, 8>,
                         cudaFuncAttributeMaxDynamicSharedMemorySize, SMEM2);
    cudaFuncSetAttribute((const void*)conv_pool_kernel<32, 32, 8, 8>,
                         cudaFuncAttributeMaxDynamicSharedMemorySize, SMEM3);

    zero_mean_kernel<<<1, 512>>>();

    // stage 1: (16,256,256,32) -> (16,127,127,16); tile 8x16 pooled
    // grid 16*8*16 = 2048 blocks -> 6.92 waves at 296 conc (98.9% fit)
    conv_pool_kernel<32, 16, 4, 16><<<dim3(16 * 8, 16), 256, SMEM1>>>(
        x, 256, W1, b1, p1, 127, 16, nullptr);

    // stage 2: (16,127,127,16) -> (16,62,62,32); tile 8x8 pooled
    conv_pool_kernel<16, 32, 8, 8><<<dim3(8 * 8, 16), 256, SMEM2>>>(
        p1, 127, W2, b2, p2, 62, 8, nullptr);

    // stage 3: (16,62,62,32) -> mean sums; tile 8x8, grid 256 <= 296 -> 1 wave
    conv_pool_kernel<32, 32, 8, 8><<<dim3(4 * 4, 16), 256, SMEM3>>>(
        p2, 62, W3, b3, nullptr, 30, 4, mean_);

    head_kernel<<<1, 256>>>(D1, db1, D2, db2, D3, db3);

    sampler_kernel<<<32768, 256>>>(x, out);
}

// round 9
// speedup vs baseline: 1.1351x; 1.1351x over previous
#include <cuda_runtime.h>
#include <cstdint>

// ---------------------------------------------------------------------------
// STN: conv(3x3)+relu+pool x3 -> mean -> dense x3 -> theta -> bilinear sample
// ---------------------------------------------------------------------------

typedef unsigned long long ull;

__device__ float g_pool1[16 * 127 * 127 * 16];
__device__ float g_pool2[16 * 62 * 62 * 32];
__device__ float g_mean[16 * 32];
__device__ float g_theta[16 * 6];

__device__ __forceinline__ void fma2(ull& d, ull a, ull b) {
    asm("fma.rn.f32x2 %0, %1, %2, %0;" : "+l"(d) : "l"(a), "l"(b));
}
__device__ __forceinline__ float2 asF2(ull v) {
    float2 r;
    r.x = __uint_as_float((unsigned)(v & 0xffffffffULL));
    r.y = __uint_as_float((unsigned)(v >> 32));
    return r;
}

// ---------------------------------------------------------------------------
// Fused conv3x3(VALID)+bias+relu+maxpool2 (+optional mean accumulation)
// fp32x2 packed over input-channel pairs; horizontal add at the end.
// Each thread: 2x4 conv positions (1x2 pooled pixels) x NC=2 output channels.
// Block: 128 thr = 4 x-slots * TILE_PY(=4) y-slots * GROUPS(=8) groups.
// Output channels split across blockIdx.z: block computes COB of COT channels.
// Small regs (~90) + small smem (23-44KB) -> 4-6 blocks/SM, 16-24 warps/SM.
// ---------------------------------------------------------------------------
template<int CIN, int COB, int GROUPS, int TILE_PY, int COT>
__global__ __launch_bounds__(128, 4)
void conv_pool_kernel(const float* __restrict__ in, int inDim,
                      const float* __restrict__ w, const float* __restrict__ bias,
                      float* __restrict__ out, int outDim, int tilesX,
                      float* __restrict__ meanAcc)
{
    constexpr int THREADS = 128;
    constexpr int NC   = COB / GROUPS;      // = 2 channels per thread
    constexpr int ISTR = CIN + 2;           // even; ISTR/2 odd -> bank spread
    constexpr int WSTR = CIN + 2;
    constexpr int TW   = 18;                // 16 conv cols + 2
    constexpr int TH   = 2 * TILE_PY + 2;   // = 10
    extern __shared__ float smem[];
    float* sIn = smem;                      // TH*TW*ISTR
    float* sW  = smem + TH * TW * ISTR;     // 9*COB*WSTR
    __shared__ float sMean[COB];

    const int tid = threadIdx.x;
    const int b  = blockIdx.y;
    const int coBase = blockIdx.z * COB;
    const int tX = blockIdx.x % tilesX;
    const int tY = blockIdx.x / tilesX;
    const int y0 = tY * TILE_PY * 2, x0 = tX * 16;

    // ---- weights: w[k][ci][coBase+co] -> sW[k][co][ci] ----
    constexpr int WTOT = 9 * CIN * COB;
    for (int i = tid; i < WTOT; i += THREADS) {
        int co = i % COB;
        int rest = i / COB;
        int ci = rest % CIN;
        int k  = rest / CIN;
        sW[(k * COB + co) * WSTR + ci] = w[(k * CIN + ci) * COT + coBase + co];
    }

    // ---- input window THxTWxCIN (channel-contiguous) ----
    constexpr int NCI4 = CIN / 4;
    for (int i = tid; i < TH * TW * NCI4; i += THREADS) {
        int ci4 = i % NCI4;
        int p   = i / NCI4;
        int ly = p / TW, lx = p - ly * TW;
        int gy = y0 + ly, gx = x0 + lx;
        float4 v = make_float4(0.f, 0.f, 0.f, 0.f);
        if (gy < inDim && gx < inDim)
            v = *(const float4*)(in + ((size_t)((b * inDim + gy) * inDim + gx)) * CIN + ci4 * 4);
        float* d = sIn + p * ISTR + ci4 * 4;        // 8B-aligned (ISTR even)
        *(ull*)(d)     = *(const ull*)&v.x;
        *(ull*)(d + 2) = *(const ull*)&v.z;
    }
    __syncthreads();

    const int g    = tid % GROUPS;
    const int slot = tid / GROUPS;
    const int sx   = slot % 4;              // conv cols 4sx..4sx+3
    const int py   = slot / 4;              // pooled row within tile

    ull acc[2][4][NC];
    #pragma unroll
    for (int i = 0; i < 2; i++)
        #pragma unroll
        for (int j = 0; j < 4; j++)
            #pragma unroll
            for (int k = 0; k < NC; k++) acc[i][j][k] = 0ULL;

    const float* ibase = sIn + ((2 * py) * TW + 4 * sx) * ISTR;
    const float* wbase = sW + g * WSTR;

    #pragma unroll 1
    for (int c2 = 0; c2 < CIN / 2; ++c2) {
        ull win[4][6];
        #pragma unroll
        for (int r = 0; r < 4; ++r)
            #pragma unroll
            for (int c = 0; c < 6; ++c)
                win[r][c] = *(const ull*)(ibase + (r * TW + c) * ISTR + 2 * c2);
        #pragma unroll
        for (int t = 0; t < 9; ++t) {
            const int ky = t / 3, kx = t % 3;
            #pragma unroll
            for (int cc = 0; cc < NC; ++cc) {
                ull w2 = *(const ull*)(wbase + (t * COB + GROUPS * cc) * WSTR + 2 * c2);
                #pragma unroll
                for (int pr = 0; pr < 2; ++pr)
                    #pragma unroll
                    for (int pc = 0; pc < 4; ++pc)
                        fma2(acc[pr][pc][cc], win[pr + ky][pc + kx], w2);
            }
        }
    }

    // ---- horizontal add + relu(max2x2 + bias), two pooled pixels ----
    const int p = tY * TILE_PY + py;
    if (meanAcc) {
        if (tid < COB) sMean[tid] = 0.f;
        __syncthreads();
    }
    #pragma unroll
    for (int j = 0; j < 2; ++j) {
        const int q = tX * 8 + 2 * sx + j;
        const bool valid = (p < outDim) && (q < outDim);
        float res[NC];
        #pragma unroll
        for (int cc = 0; cc < NC; ++cc) {
            float2 v00 = asF2(acc[0][2 * j][cc]);
            float2 v01 = asF2(acc[0][2 * j + 1][cc]);
            float2 v10 = asF2(acc[1][2 * j][cc]);
            float2 v11 = asF2(acc[1][2 * j + 1][cc]);
            float s0 = v00.x + v00.y, s1 = v01.x + v01.y;
            float s2 = v10.x + v10.y, s3 = v11.x + v11.y;
            res[cc] = fmaxf(fmaxf(fmaxf(s0, s1), fmaxf(s2, s3)) + bias[coBase + g + GROUPS * cc], 0.f);
        }
        if (out && valid) {
            float* o = out + ((size_t)((b * outDim + p) * outDim + q)) * COT + coBase;
            #pragma unroll
            for (int cc = 0; cc < NC; ++cc) o[g + GROUPS * cc] = res[cc];
        }
        if (meanAcc && valid) {
            #pragma unroll
            for (int cc = 0; cc < NC; ++cc)
                atomicAdd(&sMean[g + GROUPS * cc], res[cc]);
        }
    }
    if (meanAcc) {
        __syncthreads();
        if (tid < COB) atomicAdd(&meanAcc[b * COT + coBase + tid], sMean[tid]);
    }
}

// ---------------------------------------------------------------------------
__global__ void zero_mean_kernel() { g_mean[threadIdx.x] = 0.f; }

__global__ void head_kernel(const float* __restrict__ D1, const float* __restrict__ db1,
                            const float* __restrict__ D2, const float* __restrict__ db2,
                            const float* __restrict__ D3, const float* __restrict__ db3)
{
    __shared__ float h0[16 * 32], h1[16 * 64], h2[16 * 32];
    int tid = threadIdx.x; // 256

    for (int i = tid; i < 512; i += 256) h0[i] = g_mean[i] * (1.0f / 900.0f);
    __syncthreads();

    for (int i = tid; i < 16 * 64; i += 256) {
        int bb = i >> 6, j = i & 63;
        float s = db1[j];
        #pragma unroll 8
        for (int c = 0; c < 32; c++) s += h0[bb * 32 + c] * D1[c * 64 + j];
        h1[i] = fmaxf(s, 0.f);
    }
    __syncthreads();

    for (int i = tid; i < 512; i += 256) {
        int bb = i >> 5, j = i & 31;
        float s = db2[j];
        #pragma unroll 8
        for (int c = 0; c < 64; c++) s += h1[bb * 64 + c] * D2[c * 32 + j];
        h2[i] = fmaxf(s, 0.f);
    }
    __syncthreads();

    if (tid < 96) {
        int bb = tid / 6, j = tid % 6;
        float s = db3[j];
        #pragma unroll 8
        for (int c = 0; c < 32; c++) s += h2[bb * 32 + c] * D3[c * 6 + j];
        g_theta[tid] = s;
    }
}

// ---------------------------------------------------------------------------
__global__ __launch_bounds__(256)
void sampler_kernel(const float* __restrict__ x, float* __restrict__ out)
{
    int t = blockIdx.x * 256 + threadIdx.x;
    int lane = t & 7;
    int pix  = t >> 3;
    int c = pix & 255;
    int r = (pix >> 8) & 255;
    int b = pix >> 16;

    const float* th = g_theta + b * 6;
    float xs = -1.f + (float)c * (2.f / 255.f);
    float ys = -1.f + (float)r * (2.f / 255.f);
    float xS = th[0] * xs + th[1] * ys + th[2];
    float yS = th[3] * xs + th[4] * ys + th[5];
    float xf = 0.5f * ((xS + 1.f) * 254.f);
    float yf = 0.5f * ((yS + 1.f) * 254.f);

    int ix0 = (int)floorf(xf), iy0 = (int)floorf(yf);
    int ix1 = ix0 + 1, iy1 = iy0 + 1;
    ix0 = min(max(ix0, 0), 255); ix1 = min(max(ix1, 0), 255);
    iy0 = min(max(iy0, 0), 255); iy1 = min(max(iy1, 0), 255);

    float X0 = (float)ix0, X1 = (float)ix1, Y0 = (float)iy0, Y1 = (float)iy1;
    float wa = (X1 - xf) * (Y1 - yf);
    float wb = (X1 - xf) * (yf - Y0);
    float wc = (xf - X0) * (Y1 - yf);
    float wd = (xf - X0) * (yf - Y0);

    const float4* pa = (const float4*)(x + ((size_t)((b * 256 + iy0) * 256 + ix0)) * 32) + lane;
    const float4* pb = (const float4*)(x + ((size_t)((b * 256 + iy1) * 256 + ix0)) * 32) + lane;
    const float4* pc = (const float4*)(x + ((size_t)((b * 256 + iy0) * 256 + ix1)) * 32) + lane;
    const float4* pd = (const float4*)(x + ((size_t)((b * 256 + iy1) * 256 + ix1)) * 32) + lane;
    float4 Ia = *pa, Ib = *pb, Ic = *pc, Id = *pd;

    float4 o;
    o.x = wa * Ia.x + wb * Ib.x + wc * Ic.x + wd * Id.x;
    o.y = wa * Ia.y + wb * Ib.y + wc * Ic.y + wd * Id.y;
    o.z = wa * Ia.z + wb * Ib.z + wc * Ic.z + wd * Id.z;
    o.w = wa * Ia.w + wb * Ib.w + wc * Ic.w + wd * Id.w;
    ((float4*)out)[t] = o;
}

// ---------------------------------------------------------------------------
extern "C" void kernel_launch(void* const* d_in, const int* in_sizes, int n_in,
                              void* d_out, int out_size)
{
    const float* x   = (const float*)d_in[0];
    const float* W1  = (const float*)d_in[1];
    const float* b1  = (const float*)d_in[2];
    const float* W2  = (const float*)d_in[3];
    const float* b2  = (const float*)d_in[4];
    const float* W3  = (const float*)d_in[5];
    const float* b3  = (const float*)d_in[6];
    const float* D1  = (const float*)d_in[7];
    const float* db1 = (const float*)d_in[8];
    const float* D2  = (const float*)d_in[9];
    const float* db2 = (const float*)d_in[10];
    const float* D3  = (const float*)d_in[11];
    const float* db3 = (const float*)d_in[12];
    float* out = (float*)d_out;

    float *p1, *p2, *mean_;
    cudaGetSymbolAddress((void**)&p1, g_pool1);
    cudaGetSymbolAddress((void**)&p2, g_pool2);
    cudaGetSymbolAddress((void**)&mean_, g_mean);

    // smem (floats): input 10*18*(CIN+2) + weights 9*16*(CIN+2)
    const int SMEM1 = (10 * 18 * 34 + 9 * 16 * 34) * 4;   // 44064 -> 4-5 blk/SM
    const int SMEM2 = (10 * 18 * 18 + 9 * 16 * 18) * 4;   // 23328 -> 6+  blk/SM
    const int SMEM3 = (10 * 18 * 34 + 9 * 16 * 34) * 4;   // 44064 -> 4-5 blk/SM
    cudaFuncSetAttribute((const void*)conv_pool_kernel<32, 16, 8, 4, 16>,
                         cudaFuncAttributeMaxDynamicSharedMemorySize, SMEM1);
    cudaFuncSetAttribute((const void*)conv_pool_kernel<16, 16, 8, 4, 32>,
                         cudaFuncAttributeMaxDynamicSharedMemorySize, SMEM2);
    cudaFuncSetAttribute((const void*)conv_pool_kernel<32, 16, 8, 4, 32>,
                         cudaFuncAttributeMaxDynamicSharedMemorySize, SMEM3);

    zero_mean_kernel<<<1, 512>>>();

    // stage 1: (16,256,256,32) -> (16,127,127,16); tile 8x4, 16 ch, no split
    // grid 16*32 x 16 = 8192 blocks
    conv_pool_kernel<32, 16, 8, 4, 16><<<dim3(16 * 32, 16, 1), 128, SMEM1>>>(
        x, 256, W1, b1, p1, 127, 16, nullptr);

    // stage 2: (16,127,127,16) -> (16,62,62,32); tile 8x4, 2 channel splits
    // grid 8*16 x 16 x 2 = 4096 blocks
    conv_pool_kernel<16, 16, 8, 4, 32><<<dim3(8 * 16, 16, 2), 128, SMEM2>>>(
        p1, 127, W2, b2, p2, 62, 8, nullptr);

    // stage 3: (16,62,62,32) -> mean sums; tile 8x4, 2 channel splits
    // grid 4*8 x 16 x 2 = 1024 blocks
    conv_pool_kernel<32, 16, 8, 4, 32><<<dim3(4 * 8, 16, 2), 128, SMEM3>>>(
        p2, 62, W3, b3, nullptr, 30, 4, mean_);

    head_kernel<<<1, 256>>>(D1, db1, D2, db2, D3, db3);

    sampler_kernel<<<32768, 256>>>(x, out);
}

// round 10
// speedup vs baseline: 1.2422x; 1.0943x over previous
#include <cuda_runtime.h>
#include <cstdint>

// ---------------------------------------------------------------------------
// STN: conv(3x3)+relu+pool x3 -> mean -> dense x3 -> theta -> bilinear sample
// ---------------------------------------------------------------------------

typedef unsigned long long ull;

__device__ float g_pool1[16 * 127 * 127 * 16];
__device__ float g_pool2[16 * 62 * 62 * 32];
__device__ float g_mean[16 * 32];
__device__ float g_theta[16 * 6];

__device__ __forceinline__ void fma2(ull& d, ull a, ull b) {
    asm("fma.rn.f32x2 %0, %1, %2, %0;" : "+l"(d) : "l"(a), "l"(b));
}
__device__ __forceinline__ float2 asF2(ull v) {
    float2 r;
    r.x = __uint_as_float((unsigned)(v & 0xffffffffULL));
    r.y = __uint_as_float((unsigned)(v >> 32));
    return r;
}

// one ky-row of taps: 3 kx * NC channels over 2 position-rows x 4 position-cols
template<int NC, int COB, int WSTR, int GROUPS>
__device__ __forceinline__ void do_ky(ull (&acc)[2][4][NC],
                                      const ull (&RA)[6], const ull (&RB)[6],
                                      const float* __restrict__ wk)
{
    #pragma unroll
    for (int kx = 0; kx < 3; ++kx) {
        #pragma unroll
        for (int cc = 0; cc < NC; ++cc) {
            ull w2 = *(const ull*)(wk + (kx * COB + GROUPS * cc) * WSTR);
            #pragma unroll
            for (int pc = 0; pc < 4; ++pc) {
                fma2(acc[0][pc][cc], RA[pc + kx], w2);
                fma2(acc[1][pc][cc], RB[pc + kx], w2);
            }
        }
    }
}

// ---------------------------------------------------------------------------
// Fused conv3x3(VALID)+bias+relu+maxpool2 (+optional mean accumulation)
// fp32x2 packed over input-channel pairs; horizontal add at the end.
// Rolling 2-row register window: only 12 ull of input live at any time, each
// input value loaded from smem exactly once (prevents ptxas reload churn).
// Block: 128 thr = 4 x-slots * TILE_PY y-slots * GROUPS channel groups.
// ---------------------------------------------------------------------------
template<int CIN, int COB, int GROUPS, int TILE_PY, int COT, int MAXB>
__global__ __launch_bounds__(128, MAXB)
void conv_pool_kernel(const float* __restrict__ in, int inDim,
                      const float* __restrict__ w, const float* __restrict__ bias,
                      float* __restrict__ out, int outDim, int tilesX,
                      float* __restrict__ meanAcc)
{
    constexpr int THREADS = 128;
    constexpr int NC   = COB / GROUPS;
    constexpr int ISTR = CIN + 2;           // even; ISTR/2 odd -> bank spread
    constexpr int WSTR = CIN + 2;
    constexpr int TW   = 18;                // 16 conv cols + 2
    constexpr int TH   = 2 * TILE_PY + 2;
    extern __shared__ float smem[];
    float* sIn = smem;                      // TH*TW*ISTR
    float* sW  = smem + TH * TW * ISTR;     // 9*COB*WSTR
    __shared__ float sMean[COB];

    const int tid = threadIdx.x;
    const int b  = blockIdx.y;
    const int coBase = blockIdx.z * COB;
    const int tX = blockIdx.x % tilesX;
    const int tY = blockIdx.x / tilesX;
    const int y0 = tY * TILE_PY * 2, x0 = tX * 16;

    // ---- weights: w[k][ci][coBase+co] -> sW[k][co][ci] ----
    constexpr int WTOT = 9 * CIN * COB;
    for (int i = tid; i < WTOT; i += THREADS) {
        int co = i % COB;
        int rest = i / COB;
        int ci = rest % CIN;
        int k  = rest / CIN;
        sW[(k * COB + co) * WSTR + ci] = w[(k * CIN + ci) * COT + coBase + co];
    }

    // ---- input window THxTWxCIN (channel-contiguous) ----
    constexpr int NCI4 = CIN / 4;
    for (int i = tid; i < TH * TW * NCI4; i += THREADS) {
        int ci4 = i % NCI4;
        int p   = i / NCI4;
        int ly = p / TW, lx = p - ly * TW;
        int gy = y0 + ly, gx = x0 + lx;
        float4 v = make_float4(0.f, 0.f, 0.f, 0.f);
        if (gy < inDim && gx < inDim)
            v = *(const float4*)(in + ((size_t)((b * inDim + gy) * inDim + gx)) * CIN + ci4 * 4);
        float* d = sIn + p * ISTR + ci4 * 4;        // 8B-aligned (ISTR even)
        *(ull*)(d)     = *(const ull*)&v.x;
        *(ull*)(d + 2) = *(const ull*)&v.z;
    }
    __syncthreads();

    const int g    = tid % GROUPS;
    const int slot = tid / GROUPS;
    const int sx   = slot % 4;              // conv cols 4sx..4sx+3
    const int py   = slot / 4;              // pooled row within tile

    ull acc[2][4][NC];
    #pragma unroll
    for (int i = 0; i < 2; i++)
        #pragma unroll
        for (int j = 0; j < 4; j++)
            #pragma unroll
            for (int k = 0; k < NC; k++) acc[i][j][k] = 0ULL;

    const float* ibase = sIn + ((2 * py) * TW + 4 * sx) * ISTR;
    const float* wbase = sW + g * WSTR;

    #pragma unroll 1
    for (int c2 = 0; c2 < CIN / 2; ++c2) {
        const float* ibc = ibase + 2 * c2;
        const float* wbc = wbase + 2 * c2;
        ull r0[6], r1[6], r2[6], r3[6];
        #pragma unroll
        for (int c = 0; c < 6; ++c) r0[c] = *(const ull*)(ibc + c * ISTR);
        #pragma unroll
        for (int c = 0; c < 6; ++c) r1[c] = *(const ull*)(ibc + (TW + c) * ISTR);
        do_ky<NC, COB, WSTR, GROUPS>(acc, r0, r1, wbc);
        #pragma unroll
        for (int c = 0; c < 6; ++c) r2[c] = *(const ull*)(ibc + (2 * TW + c) * ISTR);
        do_ky<NC, COB, WSTR, GROUPS>(acc, r1, r2, wbc + 3 * COB * WSTR);
        #pragma unroll
        for (int c = 0; c < 6; ++c) r3[c] = *(const ull*)(ibc + (3 * TW + c) * ISTR);
        do_ky<NC, COB, WSTR, GROUPS>(acc, r2, r3, wbc + 6 * COB * WSTR);
    }

    // ---- horizontal add + relu(max2x2 + bias), two pooled pixels ----
    const int p = tY * TILE_PY + py;
    if (meanAcc) {
        if (tid < COB) sMean[tid] = 0.f;
        __syncthreads();
    }
    #pragma unroll
    for (int j = 0; j < 2; ++j) {
        const int q = tX * 8 + 2 * sx + j;
        const bool valid = (p < outDim) && (q < outDim);
        float res[NC];
        #pragma unroll
        for (int cc = 0; cc < NC; ++cc) {
            float2 v00 = asF2(acc[0][2 * j][cc]);
            float2 v01 = asF2(acc[0][2 * j + 1][cc]);
            float2 v10 = asF2(acc[1][2 * j][cc]);
            float2 v11 = asF2(acc[1][2 * j + 1][cc]);
            float s0 = v00.x + v00.y, s1 = v01.x + v01.y;
            float s2 = v10.x + v10.y, s3 = v11.x + v11.y;
            res[cc] = fmaxf(fmaxf(fmaxf(s0, s1), fmaxf(s2, s3)) + bias[coBase + g + GROUPS * cc], 0.f);
        }
        if (out && valid) {
            float* o = out + ((size_t)((b * outDim + p) * outDim + q)) * COT + coBase;
            #pragma unroll
            for (int cc = 0; cc < NC; ++cc) o[g + GROUPS * cc] = res[cc];
        }
        if (meanAcc && valid) {
            #pragma unroll
            for (int cc = 0; cc < NC; ++cc)
                atomicAdd(&sMean[g + GROUPS * cc], res[cc]);
        }
    }
    if (meanAcc) {
        __syncthreads();
        if (tid < COB) atomicAdd(&meanAcc[b * COT + coBase + tid], sMean[tid]);
    }
}

// ---------------------------------------------------------------------------
__global__ void zero_mean_kernel() { g_mean[threadIdx.x] = 0.f; }

__global__ void head_kernel(const float* __restrict__ D1, const float* __restrict__ db1,
                            const float* __restrict__ D2, const float* __restrict__ db2,
                            const float* __restrict__ D3, const float* __restrict__ db3)
{
    __shared__ float h0[16 * 32], h1[16 * 64], h2[16 * 32];
    int tid = threadIdx.x; // 256

    for (int i = tid; i < 512; i += 256) h0[i] = g_mean[i] * (1.0f / 900.0f);
    __syncthreads();

    for (int i = tid; i < 16 * 64; i += 256) {
        int bb = i >> 6, j = i & 63;
        float s = db1[j];
        #pragma unroll 8
        for (int c = 0; c < 32; c++) s += h0[bb * 32 + c] * D1[c * 64 + j];
        h1[i] = fmaxf(s, 0.f);
    }
    __syncthreads();

    for (int i = tid; i < 512; i += 256) {
        int bb = i >> 5, j = i & 31;
        float s = db2[j];
        #pragma unroll 8
        for (int c = 0; c < 64; c++) s += h1[bb * 64 + c] * D2[c * 32 + j];
        h2[i] = fmaxf(s, 0.f);
    }
    __syncthreads();

    if (tid < 96) {
        int bb = tid / 6, j = tid % 6;
        float s = db3[j];
        #pragma unroll 8
        for (int c = 0; c < 32; c++) s += h2[bb * 32 + c] * D3[c * 6 + j];
        g_theta[tid] = s;
    }
}

// ---------------------------------------------------------------------------
__global__ __launch_bounds__(256)
void sampler_kernel(const float* __restrict__ x, float* __restrict__ out)
{
    int t = blockIdx.x * 256 + threadIdx.x;
    int lane = t & 7;
    int pix  = t >> 3;
    int c = pix & 255;
    int r = (pix >> 8) & 255;
    int b = pix >> 16;

    const float* th = g_theta + b * 6;
    float xs = -1.f + (float)c * (2.f / 255.f);
    float ys = -1.f + (float)r * (2.f / 255.f);
    float xS = th[0] * xs + th[1] * ys + th[2];
    float yS = th[3] * xs + th[4] * ys + th[5];
    float xf = 0.5f * ((xS + 1.f) * 254.f);
    float yf = 0.5f * ((yS + 1.f) * 254.f);

    int ix0 = (int)floorf(xf), iy0 = (int)floorf(yf);
    int ix1 = ix0 + 1, iy1 = iy0 + 1;
    ix0 = min(max(ix0, 0), 255); ix1 = min(max(ix1, 0), 255);
    iy0 = min(max(iy0, 0), 255); iy1 = min(max(iy1, 0), 255);

    float X0 = (float)ix0, X1 = (float)ix1, Y0 = (float)iy0, Y1 = (float)iy1;
    float wa = (X1 - xf) * (Y1 - yf);
    float wb = (X1 - xf) * (yf - Y0);
    float wc = (xf - X0) * (Y1 - yf);
    float wd = (xf - X0) * (yf - Y0);

    const float4* pa = (const float4*)(x + ((size_t)((b * 256 + iy0) * 256 + ix0)) * 32) + lane;
    const float4* pb = (const float4*)(x + ((size_t)((b * 256 + iy1) * 256 + ix0)) * 32) + lane;
    const float4* pc = (const float4*)(x + ((size_t)((b * 256 + iy0) * 256 + ix1)) * 32) + lane;
    const float4* pd = (const float4*)(x + ((size_t)((b * 256 + iy1) * 256 + ix1)) * 32) + lane;
    float4 Ia = *pa, Ib = *pb, Ic = *pc, Id = *pd;

    float4 o;
    o.x = wa * Ia.x + wb * Ib.x + wc * Ic.x + wd * Id.x;
    o.y = wa * Ia.y + wb * Ib.y + wc * Ic.y + wd * Id.y;
    o.z = wa * Ia.z + wb * Ib.z + wc * Ic.z + wd * Id.z;
    o.w = wa * Ia.w + wb * Ib.w + wc * Ic.w + wd * Id.w;
    ((float4*)out)[t] = o;
}

// ---------------------------------------------------------------------------
extern "C" void kernel_launch(void* const* d_in, const int* in_sizes, int n_in,
                              void* d_out, int out_size)
{
    const float* x   = (const float*)d_in[0];
    const float* W1  = (const float*)d_in[1];
    const float* b1  = (const float*)d_in[2];
    const float* W2  = (const float*)d_in[3];
    const float* b2  = (const float*)d_in[4];
    const float* W3  = (const float*)d_in[5];
    const float* b3  = (const float*)d_in[6];
    const float* D1  = (const float*)d_in[7];
    const float* db1 = (const float*)d_in[8];
    const float* D2  = (const float*)d_in[9];
    const float* db2 = (const float*)d_in[10];
    const float* D3  = (const float*)d_in[11];
    const float* db3 = (const float*)d_in[12];
    float* out = (float*)d_out;

    float *p1, *p2, *mean_;
    cudaGetSymbolAddress((void**)&p1, g_pool1);
    cudaGetSymbolAddress((void**)&p2, g_pool2);
    cudaGetSymbolAddress((void**)&mean_, g_mean);

    // smem (floats): input TH*18*(CIN+2) + weights 9*COB*(CIN+2)
    const int SMEM1 = (18 * 18 * 34 + 9 * 16 * 34) * 4;   // 63648 -> 3 blk/SM
    const int SMEM2 = (10 * 18 * 18 + 9 * 32 * 18) * 4;   // 33696 -> 4 blk/SM
    const int SMEM3 = (10 * 18 * 34 + 9 * 16 * 34) * 4;   // 44064 -> 4 blk/SM
    cudaFuncSetAttribute((const void*)conv_pool_kernel<32, 16, 4, 8, 16, 3>,
                         cudaFuncAttributeMaxDynamicSharedMemorySize, SMEM1);
    cudaFuncSetAttribute((const void*)conv_pool_kernel<16, 32, 8, 4, 32, 4>,
                         cudaFuncAttributeMaxDynamicSharedMemorySize, SMEM2);
    cudaFuncSetAttribute((const void*)conv_pool_kernel<32, 16, 8, 4, 32, 4>,
                         cudaFuncAttributeMaxDynamicSharedMemorySize, SMEM3);

    zero_mean_kernel<<<1, 512>>>();

    // stage 1: (16,256,256,32) -> (16,127,127,16); tile 8x8 pooled, NC=4
    conv_pool_kernel<32, 16, 4, 8, 16, 3><<<dim3(16 * 16, 16, 1), 128, SMEM1>>>(
        x, 256, W1, b1, p1, 127, 16, nullptr);

    // stage 2: (16,127,127,16) -> (16,62,62,32); tile 8x4 pooled, NC=4
    conv_pool_kernel<16, 32, 8, 4, 32, 4><<<dim3(8 * 16, 16, 1), 128, SMEM2>>>(
        p1, 127, W2, b2, p2, 62, 8, nullptr);

    // stage 3: (16,62,62,32) -> mean sums; tile 8x4, NC=2, 2 channel splits
    conv_pool_kernel<32, 16, 8, 4, 32, 4><<<dim3(4 * 8, 16, 2), 128, SMEM3>>>(
        p2, 62, W3, b3, nullptr, 30, 4, mean_);

    head_kernel<<<1, 256>>>(D1, db1, D2, db2, D3, db3);

    sampler_kernel<<<32768, 256>>>(x, out);
}